// round 9
// baseline (speedup 1.0000x reference)
#include <cuda_runtime.h>
#include <cstdint>

// ---------------- problem dims ----------------
#define K_HALF 24
#define S_DIM  64
#define D_DIM  256
#define L_DIM  1024
#define B_SZ   4
#define KX     8
#define O_DIM  48                      // 2*K_HALF
#define K_G    16384                   // D_DIM * S_DIM  (k = d*64 + s)
#define K_TOT  18432                   // K_G + KX*D_DIM (k = 16384 + j*256 + d)
#define M_ROWS 4096                    // B_SZ * L_DIM
#define E_DIM  256
#define KSPLIT 4

// ---------------- scratch (device globals; no cudaMalloc allowed) ----------------
__device__ float g_Pt[(size_t)E_DIM * K_TOT];                  // 19 MB: [e][k] (B, K-major, tf32)
__device__ float g_ck[(size_t)(M_ROWS / 16) * K_G];            // 16 MB: scan state entering each 16-row block
__device__ float g_part[KSPLIT][(size_t)M_ROWS * E_DIM];       // 16 MB: split-K partials

// ---------------- helpers ----------------
__device__ __forceinline__ uint32_t smem_u32(const void* p) {
    uint32_t a;
    asm("{ .reg .u64 t; cvta.to.shared.u64 t, %1; cvt.u32.u64 %0, t; }" : "=r"(a) : "l"(p));
    return a;
}

__device__ __forceinline__ float to_tf32(float v) {
    uint32_t u;
    asm("cvt.rna.tf32.f32 %0, %1;" : "=r"(u) : "f"(v));
    return __uint_as_float(u);
}

__device__ __forceinline__ void cp_async16(uint32_t dst, const void* src) {
    asm volatile("cp.async.cg.shared.global [%0], [%1], 16;" :: "r"(dst), "l"(src));
}
__device__ __forceinline__ void cp_commit() {
    asm volatile("cp.async.commit_group;" ::: "memory");
}

// m16n8k8 tf32 mma, D += A*B (fp32 accum in place)
__device__ __forceinline__ void mma8(float* d, const uint32_t* a, const uint32_t* b) {
    asm volatile(
        "mma.sync.aligned.m16n8k8.row.col.f32.tf32.tf32.f32 "
        "{%0,%1,%2,%3},{%4,%5,%6,%7},{%8,%9},{%0,%1,%2,%3};"
        : "+f"(d[0]), "+f"(d[1]), "+f"(d[2]), "+f"(d[3])
        : "r"(a[0]), "r"(a[1]), "r"(a[2]), "r"(a[3]), "r"(b[0]), "r"(b[1]));
}

__device__ __forceinline__ void ldsm4(uint32_t* r, uint32_t addr) {
    asm volatile("ldmatrix.sync.aligned.m8n8.x4.shared.b16 {%0,%1,%2,%3}, [%4];"
        : "=r"(r[0]), "=r"(r[1]), "=r"(r[2]), "=r"(r[3]) : "r"(addr));
}

__device__ __forceinline__ void sts32(uint32_t addr, float v) {
    asm volatile("st.shared.b32 [%0], %1;" :: "r"(addr), "f"(v));
}

// ---------------- kernel: precompute Pt[e][k] (tf32-rounded), half-d per call ----
__global__ void k_prep(const float* __restrict__ C, const float* __restrict__ Bv,
                       const float* __restrict__ M, const float* __restrict__ Mp,
                       const float* __restrict__ Mm, int d0) {
    __shared__ float Wsh[O_DIM * E_DIM];   // 48 KB
    int d   = blockIdx.x + d0;
    int tid = threadIdx.x;
    int s   = tid & 63;
    int eg  = tid >> 6;

    for (int i = tid; i < O_DIM * E_DIM; i += 256) {
        int o = i >> 8, e = i & 255;
        Wsh[i] = (o < K_HALF) ? Mp[((size_t)o * D_DIM + d) * D_DIM + e]
                              : Mm[((size_t)(o - K_HALF) * D_DIM + d) * D_DIM + e];
    }
    __syncthreads();

    float cs[O_DIM];
#pragma unroll
    for (int o = 0; o < O_DIM; o++) cs[o] = C[s * O_DIM + o];
    float bv = Bv[s];

    for (int e = eg * 64; e < eg * 64 + 64; e++) {
        float acc = 0.0f;
#pragma unroll
        for (int o = 0; o < O_DIM; o++)
            acc = fmaf(cs[o], Wsh[o * E_DIM + e], acc);
        g_Pt[(size_t)e * K_TOT + d * S_DIM + s] = to_tf32(bv * acc);
    }

    if (s < KX) {
        int j = s;
        float mj[O_DIM];
#pragma unroll
        for (int o = 0; o < O_DIM; o++) mj[o] = M[o * KX + j];   // M is (48, 8, 1)
        for (int e = eg * 64; e < eg * 64 + 64; e++) {
            float acc = 0.0f;
#pragma unroll
            for (int o = 0; o < O_DIM; o++)
                acc = fmaf(mj[o], Wsh[o * E_DIM + e], acc);
            g_Pt[(size_t)e * K_TOT + K_G + j * D_DIM + d] = to_tf32(acc);
        }
    }
}

// ---------------- kernel: scan checkpoints every 16 rows ----------------
__global__ void k_ckpt(const float* __restrict__ x, const float* __restrict__ A) {
    int s    = threadIdx.x & 63;
    int half = threadIdx.x >> 6;
    int bd   = blockIdx.x * 2 + half;   // 0..1023
    int b    = bd >> 8;
    int d    = bd & 255;

    float a = A[s];
    float h = 0.0f;
    const float* xp = x + (size_t)b * L_DIM * D_DIM + d;
    float* cp = g_ck + (size_t)(b * (L_DIM / 16)) * K_G + d * S_DIM + s;

#pragma unroll 1
    for (int lb = 0; lb < L_DIM / 16; lb++) {
        cp[(size_t)lb * K_G] = h;       // state entering row lb*16
#pragma unroll
        for (int i = 0; i < 16; i++)
            h = fmaf(h, a, xp[(size_t)(lb * 16 + i) * D_DIM]);
    }
}

// ---------------- fused GEMM  part[ki][m][e] += A[m][k]*Pt[e][k] over chunk ----
// CTA tile 128(M) x 128(N), 256 threads (8 warps 2x4, warp 64x32), KT=32.
// 2 CTAs/SM (64 KB smem each): one CTA's mma covers the other's producer/barrier.
#define KT    32
#define KCH   (K_TOT / KSPLIT)          // 4608
#define NSTG  (KCH / KT)                // 144
#define A_STG 16384                     // 128 rows * 128B
#define B_STG 16384                     // 128 rows * 128B
#define SMEM_DYN (2 * A_STG + 2 * B_STG)  // 65536

__global__ void __launch_bounds__(256, 2)
k_gemm(const float* __restrict__ x, const float* __restrict__ A) {
    extern __shared__ char smem[];
    uint32_t sb  = smem_u32(smem);
    uint32_t sbB = sb + 2 * A_STG;

    int tid  = threadIdx.x;
    int lane = tid & 31;
    int wid  = tid >> 5;                 // 0..7
    int wm   = wid >> 2;                 // 0..1
    int wn   = wid & 3;                  // 0..3
    int mi   = blockIdx.x;               // 0..31
    int ni   = blockIdx.y;               // 0..1
    int ki   = blockIdx.z;               // 0..3
    int m0   = mi * 128;
    int n0   = ni * 128;
    int k0   = ki * KCH;

    // producer coords: pc = column in 32-col stage, plb = 16-row block (0..7)
    int pc   = tid & 31;
    int plb  = tid >> 5;
    float a_reg0 = A[pc];
    float a_reg1 = A[pc + 32];
    size_t ckrow = (size_t)(mi * 8 + plb) * K_G;

    // checkpoint load for stage st (0 if out of range / shift stage)
    auto load_ck = [&](int st) -> float {
        int k = k0 + st * KT;
        if (st < NSTG && k < K_G)
            return g_ck[ckrow + (size_t)(k >> 6) * S_DIM + (k & 32) + pc];
        return 0.0f;
    };

    // produce A stage st (128 rows x 32 cols) into buffer p
    auto produce = [&](int st, int p, float ck) {
        int k = k0 + st * KT;
        uint32_t abase = sb + p * A_STG;
        if (k < K_G) {
            int d = k >> 6;
            float a = (k & 32) ? a_reg1 : a_reg0;
            float h = ck;
            const float* xp = x + (size_t)(m0 + plb * 16) * D_DIM + d;
#pragma unroll
            for (int i = 0; i < 16; i++) {
                h = fmaf(h, a, xp[(size_t)i * D_DIM]);
                int r = plb * 16 + i;
                sts32(abase + r * 128 + (((pc >> 2) ^ (r & 7)) << 4) + ((pc & 3) << 2),
                      to_tf32(h));
            }
        } else {
            int off = k - K_G;
            int j   = off >> 8;
            int dd  = (off & 255) + pc;
            const float* xp = x + (size_t)(m0 + plb * 16 - j) * D_DIM + dd;
#pragma unroll
            for (int i = 0; i < 16; i++) {
                int gl = (m0 + plb * 16 + i) & (L_DIM - 1);
                float v = (gl >= j) ? xp[(size_t)i * D_DIM] : 0.0f;
                int r = plb * 16 + i;
                sts32(abase + r * 128 + (((pc >> 2) ^ (r & 7)) << 4) + ((pc & 3) << 2),
                      to_tf32(v));
            }
        }
    };

    // cp.async B stage st (rows n0..n0+127, 32 cols) into buffer p
    auto cpB = [&](int st, int p) {
        uint32_t base = sbB + p * B_STG;
        int kf = k0 + st * KT;
#pragma unroll
        for (int q = 0; q < 4; q++) {
            int id = tid + q * 256;                 // 0..1023 16B chunks
            int r  = id >> 3;                       // e row (0..127)
            int ch = id & 7;
            cp_async16(base + r * 128 + ((ch ^ (r & 7)) << 4),
                       g_Pt + (size_t)(n0 + r) * K_TOT + kf + ch * 4);
        }
    };

    float acc[4][4][4];
#pragma unroll
    for (int i = 0; i < 4; i++)
#pragma unroll
        for (int j = 0; j < 4; j++)
#pragma unroll
            for (int c = 0; c < 4; c++) acc[i][j][c] = 0.0f;

    // ldmatrix per-lane address components (validated rounds 2-8):
    int sw   = lane & 7;
    int aRow = (lane & 7) + (((lane >> 3) & 1) << 3);
    int aCb  = lane >> 4;
    int bRow = (lane & 7) + ((lane >> 4) << 3);
    int bCb  = (lane >> 3) & 1;

    int lr = lane >> 2;
    int lc = lane & 3;

    // prologue
    produce(0, 0, load_ck(0));
    float ck_next = load_ck(1);
    cpB(0, 0); cp_commit();

    for (int ks = 0; ks < NSTG; ks++) {
        asm volatile("cp.async.wait_group 0;" ::: "memory");   // B(ks) complete
        __syncthreads();                                       // A(ks) visible; bufs free
        if (ks + 1 < NSTG) { cpB(ks + 1, (ks + 1) & 1); cp_commit(); }

        uint32_t aT = sb  + (ks & 1) * A_STG;
        uint32_t bT = sbB + (ks & 1) * B_STG;
        uint32_t aLane = aT + (wm * 64 + aRow) * 128;
        uint32_t bLane = bT + (wn * 32 + bRow) * 128;

        // ---- mma kk = 0,1 ----
#pragma unroll
        for (int kk = 0; kk < 2; kk++) {
            uint32_t bF[8];
#pragma unroll
            for (int nfp = 0; nfp < 2; nfp++)
                ldsm4(&bF[nfp * 4],
                      bLane + nfp * 16 * 128 + (((2 * kk + bCb) ^ sw) << 4));
            uint32_t aF[16];
#pragma unroll
            for (int mf = 0; mf < 4; mf++)
                ldsm4(&aF[mf * 4],
                      aLane + mf * 16 * 128 + (((2 * kk + aCb) ^ sw) << 4));
#pragma unroll
            for (int mf = 0; mf < 4; mf++)
#pragma unroll
                for (int nf = 0; nf < 4; nf++)
                    mma8(acc[mf][nf], &aF[mf * 4],
                         &bF[(nf >> 1) * 4 + (nf & 1) * 2]);
        }

        // ---- producer for stage ks+1 (overlapped with mma) ----
        if (ks + 1 < NSTG) produce(ks + 1, (ks + 1) & 1, ck_next);
        ck_next = load_ck(ks + 2);

        // ---- mma kk = 2,3 ----
#pragma unroll
        for (int kk = 2; kk < 4; kk++) {
            uint32_t bF[8];
#pragma unroll
            for (int nfp = 0; nfp < 2; nfp++)
                ldsm4(&bF[nfp * 4],
                      bLane + nfp * 16 * 128 + (((2 * kk + bCb) ^ sw) << 4));
            uint32_t aF[16];
#pragma unroll
            for (int mf = 0; mf < 4; mf++)
                ldsm4(&aF[mf * 4],
                      aLane + mf * 16 * 128 + (((2 * kk + aCb) ^ sw) << 4));
#pragma unroll
            for (int mf = 0; mf < 4; mf++)
#pragma unroll
                for (int nf = 0; nf < 4; nf++)
                    mma8(acc[mf][nf], &aF[mf * 4],
                         &bF[(nf >> 1) * 4 + (nf & 1) * 2]);
        }
    }

    // epilogue: plain stores to this split's partial buffer
    float* po = g_part[ki];
#pragma unroll
    for (int mf = 0; mf < 4; mf++) {
#pragma unroll
        for (int nf = 0; nf < 4; nf++) {
            int r = m0 + wm * 64 + mf * 16 + lr;
            int c = n0 + wn * 32 + nf * 8 + (lc << 1);
            *(float2*)&po[(size_t)r * E_DIM + c] =
                make_float2(acc[mf][nf][0], acc[mf][nf][1]);
            *(float2*)&po[(size_t)(r + 8) * E_DIM + c] =
                make_float2(acc[mf][nf][2], acc[mf][nf][3]);
        }
    }
}

// ---------------- reduce: out = sum of KSPLIT partials ----------------
__global__ void k_reduce(float* __restrict__ out, int n4) {
    int i = blockIdx.x * 256 + threadIdx.x;
    if (i >= n4) return;
    float4 a = ((const float4*)g_part[0])[i];
    float4 b = ((const float4*)g_part[1])[i];
    float4 c = ((const float4*)g_part[2])[i];
    float4 d = ((const float4*)g_part[3])[i];
    float4 r;
    r.x = (a.x + b.x) + (c.x + d.x);
    r.y = (a.y + b.y) + (c.y + d.y);
    r.z = (a.z + b.z) + (c.z + d.z);
    r.w = (a.w + b.w) + (c.w + d.w);
    ((float4*)out)[i] = r;
}

// ---------------- launch ----------------
extern "C" void kernel_launch(void* const* d_in, const int* in_sizes, int n_in,
                              void* d_out, int out_size) {
    const float* x  = (const float*)d_in[0];
    const float* A  = (const float*)d_in[1];
    const float* Bv = (const float*)d_in[2];
    const float* C  = (const float*)d_in[3];
    const float* M  = (const float*)d_in[4];
    const float* Mp = (const float*)d_in[5];
    const float* Mm = (const float*)d_in[6];
    float* out = (float*)d_out;

    static bool attr_set = false;
    if (!attr_set) {
        cudaFuncSetAttribute(k_gemm, cudaFuncAttributeMaxDynamicSharedMemorySize, SMEM_DYN);
        attr_set = true;
    }

    // k_gemm at launch #4 (the slot ncu captures).
    k_prep<<<128, 256>>>(C, Bv, M, Mp, Mm, 0);
    k_prep<<<128, 256>>>(C, Bv, M, Mp, Mm, 128);
    k_ckpt<<<512, 128>>>(x, A);

    dim3 grid(M_ROWS / 128, 2, KSPLIT);
    k_gemm<<<grid, 256, SMEM_DYN>>>(x, A);

    int n4 = M_ROWS * E_DIM / 4;
    k_reduce<<<(n4 + 255) / 256, 256>>>(out, n4);
}

// round 10
// speedup vs baseline: 1.6404x; 1.6404x over previous
#include <cuda_runtime.h>
#include <cuda_fp16.h>
#include <cstdint>

// ---------------- problem dims ----------------
#define K_HALF 24
#define S_DIM  64
#define D_DIM  256
#define L_DIM  1024
#define B_SZ   4
#define KX     8
#define O_DIM  48                      // 2*K_HALF
#define K_G    16384                   // D_DIM * S_DIM  (k = d*64 + s)
#define K_TOT  18432                   // K_G + KX*D_DIM (k = 16384 + j*256 + d)
#define M_ROWS 4096                    // B_SZ * L_DIM
#define E_DIM  256
#define KSPLIT 4

// ---------------- scratch (device globals; no cudaMalloc allowed) ----------------
__device__ __half g_Pth[(size_t)E_DIM * K_TOT];                // 9.4 MB: [e][k] (B, K-major, fp16)
__device__ float  g_ck[(size_t)(M_ROWS / 16) * K_G];           // 16 MB: scan state entering each 16-row block
__device__ float  g_part[KSPLIT][(size_t)M_ROWS * E_DIM];      // 16 MB: split-K partials

// ---------------- helpers ----------------
__device__ __forceinline__ uint32_t smem_u32(const void* p) {
    uint32_t a;
    asm("{ .reg .u64 t; cvta.to.shared.u64 t, %1; cvt.u32.u64 %0, t; }" : "=r"(a) : "l"(p));
    return a;
}

__device__ __forceinline__ void cp_async16(uint32_t dst, const void* src) {
    asm volatile("cp.async.cg.shared.global [%0], [%1], 16;" :: "r"(dst), "l"(src));
}
__device__ __forceinline__ void cp_commit() {
    asm volatile("cp.async.commit_group;" ::: "memory");
}

// m16n8k16 fp16 mma, fp32 accumulate in place
__device__ __forceinline__ void mma16(float* d, const uint32_t* a, uint32_t b0, uint32_t b1) {
    asm volatile(
        "mma.sync.aligned.m16n8k16.row.col.f32.f16.f16.f32 "
        "{%0,%1,%2,%3},{%4,%5,%6,%7},{%8,%9},{%0,%1,%2,%3};"
        : "+f"(d[0]), "+f"(d[1]), "+f"(d[2]), "+f"(d[3])
        : "r"(a[0]), "r"(a[1]), "r"(a[2]), "r"(a[3]), "r"(b0), "r"(b1));
}

__device__ __forceinline__ void ldsm4(uint32_t* r, uint32_t addr) {
    asm volatile("ldmatrix.sync.aligned.m8n8.x4.shared.b16 {%0,%1,%2,%3}, [%4];"
        : "=r"(r[0]), "=r"(r[1]), "=r"(r[2]), "=r"(r[3]) : "r"(addr));
}

__device__ __forceinline__ void sts16(uint32_t addr, __half v) {
    unsigned short u = __half_as_ushort(v);
    asm volatile("st.shared.u16 [%0], %1;" :: "r"(addr), "h"(u));
}

// ---------------- kernel: precompute Pt[e][k] (fp16), half-d per call ----------
__global__ void k_prep(const float* __restrict__ C, const float* __restrict__ Bv,
                       const float* __restrict__ M, const float* __restrict__ Mp,
                       const float* __restrict__ Mm, int d0) {
    __shared__ float Wsh[O_DIM * E_DIM];   // 48 KB
    int d   = blockIdx.x + d0;
    int tid = threadIdx.x;
    int s   = tid & 63;
    int eg  = tid >> 6;

    for (int i = tid; i < O_DIM * E_DIM; i += 256) {
        int o = i >> 8, e = i & 255;
        Wsh[i] = (o < K_HALF) ? Mp[((size_t)o * D_DIM + d) * D_DIM + e]
                              : Mm[((size_t)(o - K_HALF) * D_DIM + d) * D_DIM + e];
    }
    __syncthreads();

    float cs[O_DIM];
#pragma unroll
    for (int o = 0; o < O_DIM; o++) cs[o] = C[s * O_DIM + o];
    float bv = Bv[s];

    for (int e = eg * 64; e < eg * 64 + 64; e++) {
        float acc = 0.0f;
#pragma unroll
        for (int o = 0; o < O_DIM; o++)
            acc = fmaf(cs[o], Wsh[o * E_DIM + e], acc);
        g_Pth[(size_t)e * K_TOT + d * S_DIM + s] = __float2half_rn(bv * acc);
    }

    if (s < KX) {
        int j = s;
        float mj[O_DIM];
#pragma unroll
        for (int o = 0; o < O_DIM; o++) mj[o] = M[o * KX + j];   // M is (48, 8, 1)
        for (int e = eg * 64; e < eg * 64 + 64; e++) {
            float acc = 0.0f;
#pragma unroll
            for (int o = 0; o < O_DIM; o++)
                acc = fmaf(mj[o], Wsh[o * E_DIM + e], acc);
            g_Pth[(size_t)e * K_TOT + K_G + j * D_DIM + d] = __float2half_rn(acc);
        }
    }
}

// ---------------- kernel: scan checkpoints every 16 rows (fp32) ----------------
__global__ void k_ckpt(const float* __restrict__ x, const float* __restrict__ A) {
    int s    = threadIdx.x & 63;
    int half = threadIdx.x >> 6;
    int bd   = blockIdx.x * 2 + half;   // 0..1023
    int b    = bd >> 8;
    int d    = bd & 255;

    float a = A[s];
    float h = 0.0f;
    const float* xp = x + (size_t)b * L_DIM * D_DIM + d;
    float* cp = g_ck + (size_t)(b * (L_DIM / 16)) * K_G + d * S_DIM + s;

#pragma unroll 1
    for (int lb = 0; lb < L_DIM / 16; lb++) {
        cp[(size_t)lb * K_G] = h;       // state entering row lb*16
#pragma unroll
        for (int i = 0; i < 16; i++)
            h = fmaf(h, a, xp[(size_t)(lb * 16 + i) * D_DIM]);
    }
}

// ---------------- fused fp16 GEMM  part[ki][m][e] = sum_k A[m][k]*Pt[e][k] -----
// CTA 128(M) x 256(N), 512 threads (16 warps 2x8, warp 64x32). KT=64 fp16 cols
// = 128B rows. A produced in-kernel (scan from checkpoints / shifted-x), B via
// cp.async of fp16 Pt. Producer sandwiched between mma k-step halves.
#define KT    64
#define KCH   (K_TOT / KSPLIT)          // 4608
#define NSTG  (KCH / KT)                // 72
#define A_STG 16384                     // 128 rows * 128B (64 fp16)
#define B_STG 32768                     // 256 rows * 128B
#define SMEM_DYN (2 * A_STG + 2 * B_STG)  // 98304

__global__ void __launch_bounds__(512, 1)
k_gemm(const float* __restrict__ x, const float* __restrict__ A) {
    extern __shared__ char smem[];
    uint32_t sb  = smem_u32(smem);
    uint32_t sbB = sb + 2 * A_STG;

    int tid  = threadIdx.x;
    int lane = tid & 31;
    int wid  = tid >> 5;                 // 0..15
    int wm   = wid >> 3;                 // 0..1
    int wn   = wid & 7;                  // 0..7
    int mi   = blockIdx.x;               // 0..31
    int ki   = blockIdx.y;               // 0..3
    int m0   = mi * 128;
    int k0   = ki * KCH;

    // producer coords: pc = column in 64-col stage, plb = 16-row block (0..7)
    int pc   = tid & 63;
    int plb  = tid >> 6;
    float a_reg = A[pc];
    size_t ckrow = (size_t)(mi * 8 + plb) * K_G;

    auto load_ck = [&](int st) -> float {
        int k = k0 + st * KT;
        if (st < NSTG && k < K_G)
            return g_ck[ckrow + (size_t)(k >> 6) * S_DIM + pc];
        return 0.0f;
    };

    // produce A stage st (128 rows x 64 fp16 cols) into buffer p
    auto produce = [&](int st, int p, float ck) {
        int k = k0 + st * KT;
        uint32_t abase = sb + p * A_STG;
        uint32_t cbyte = (pc & 7) * 2;
        uint32_t cchk  = pc >> 3;
        if (k < K_G) {
            int d = k >> 6;
            float h = ck;
            const float* xp = x + (size_t)(m0 + plb * 16) * D_DIM + d;
#pragma unroll
            for (int i = 0; i < 16; i++) {
                h = fmaf(h, a_reg, xp[(size_t)i * D_DIM]);
                int r = plb * 16 + i;
                sts16(abase + r * 128 + ((cchk ^ (r & 7)) << 4) + cbyte,
                      __float2half_rn(h));
            }
        } else {
            int off = k - K_G;
            int j   = off >> 8;
            int dd  = (off & 255) + pc;
            const float* xp = x + (size_t)(m0 + plb * 16 - j) * D_DIM + dd;
#pragma unroll
            for (int i = 0; i < 16; i++) {
                int gl = (m0 + plb * 16 + i) & (L_DIM - 1);
                float v = (gl >= j) ? xp[(size_t)i * D_DIM] : 0.0f;
                int r = plb * 16 + i;
                sts16(abase + r * 128 + ((cchk ^ (r & 7)) << 4) + cbyte,
                      __float2half_rn(v));
            }
        }
    };

    // cp.async B stage st (256 e-rows x 64 fp16) into buffer p
    auto cpB = [&](int st, int p) {
        uint32_t base = sbB + p * B_STG;
        int kf = k0 + st * KT;
#pragma unroll
        for (int q = 0; q < 4; q++) {
            int id = tid + q * 512;                 // 0..2047 16B chunks
            int r  = id >> 3;                       // e row (0..255)
            int ch = id & 7;                        // 8 fp16 per chunk
            cp_async16(base + r * 128 + ((ch ^ (r & 7)) << 4),
                       g_Pth + (size_t)r * K_TOT + kf + ch * 8);
        }
    };

    float acc[4][4][4];
#pragma unroll
    for (int i = 0; i < 4; i++)
#pragma unroll
        for (int j = 0; j < 4; j++)
#pragma unroll
            for (int c = 0; c < 4; c++) acc[i][j][c] = 0.0f;

    // ldmatrix per-lane address components: the lane->matrix map makes
    // aF = {m0-7/kLo, m8-15/kLo, m0-7/kHi, m8-15/kHi} = canonical a0..a3, and
    // bF = {n0-7/kLo, n0-7/kHi, n8-15/kLo, n8-15/kHi} (validated rounds 2-9).
    int sw   = lane & 7;
    int aRow = (lane & 7) + (((lane >> 3) & 1) << 3);
    int aCb  = lane >> 4;
    int bRow = (lane & 7) + ((lane >> 4) << 3);
    int bCb  = (lane >> 3) & 1;

    int lr = lane >> 2;
    int lc = lane & 3;

    // prologue
    produce(0, 0, load_ck(0));
    float ck_next = load_ck(1);
    cpB(0, 0); cp_commit();

    for (int ks = 0; ks < NSTG; ks++) {
        asm volatile("cp.async.wait_group 0;" ::: "memory");   // B(ks) complete
        __syncthreads();                                       // A(ks) visible; bufs free
        if (ks + 1 < NSTG) { cpB(ks + 1, (ks + 1) & 1); cp_commit(); }

        uint32_t aT = sb  + (ks & 1) * A_STG;
        uint32_t bT = sbB + (ks & 1) * B_STG;
        uint32_t aLane = aT + (wm * 64 + aRow) * 128;
        uint32_t bLane = bT + (wn * 32 + bRow) * 128;

        // ---- mma k-steps 0,1 (k cols 0..31) ----
#pragma unroll
        for (int kk = 0; kk < 2; kk++) {
            uint32_t bF[8];
#pragma unroll
            for (int nfp = 0; nfp < 2; nfp++)
                ldsm4(&bF[nfp * 4],
                      bLane + nfp * 16 * 128 + (((2 * kk + bCb) ^ sw) << 4));
            uint32_t aF[16];
#pragma unroll
            for (int mf = 0; mf < 4; mf++)
                ldsm4(&aF[mf * 4],
                      aLane + mf * 16 * 128 + (((2 * kk + aCb) ^ sw) << 4));
#pragma unroll
            for (int mf = 0; mf < 4; mf++)
#pragma unroll
                for (int nf = 0; nf < 4; nf++)
                    mma16(acc[mf][nf], &aF[mf * 4],
                          bF[(nf >> 1) * 4 + (nf & 1) * 2],
                          bF[(nf >> 1) * 4 + (nf & 1) * 2 + 1]);
        }

        // ---- producer for stage ks+1 (overlapped with mma) ----
        if (ks + 1 < NSTG) produce(ks + 1, (ks + 1) & 1, ck_next);
        ck_next = load_ck(ks + 2);

        // ---- mma k-steps 2,3 (k cols 32..63) ----
#pragma unroll
        for (int kk = 2; kk < 4; kk++) {
            uint32_t bF[8];
#pragma unroll
            for (int nfp = 0; nfp < 2; nfp++)
                ldsm4(&bF[nfp * 4],
                      bLane + nfp * 16 * 128 + (((2 * kk + bCb) ^ sw) << 4));
            uint32_t aF[16];
#pragma unroll
            for (int mf = 0; mf < 4; mf++)
                ldsm4(&aF[mf * 4],
                      aLane + mf * 16 * 128 + (((2 * kk + aCb) ^ sw) << 4));
#pragma unroll
            for (int mf = 0; mf < 4; mf++)
#pragma unroll
                for (int nf = 0; nf < 4; nf++)
                    mma16(acc[mf][nf], &aF[mf * 4],
                          bF[(nf >> 1) * 4 + (nf & 1) * 2],
                          bF[(nf >> 1) * 4 + (nf & 1) * 2 + 1]);
        }
    }

    // epilogue: plain stores to this split's partial buffer
    float* po = g_part[ki];
#pragma unroll
    for (int mf = 0; mf < 4; mf++) {
#pragma unroll
        for (int nf = 0; nf < 4; nf++) {
            int r = m0 + wm * 64 + mf * 16 + lr;
            int c = wn * 32 + nf * 8 + (lc << 1);
            *(float2*)&po[(size_t)r * E_DIM + c] =
                make_float2(acc[mf][nf][0], acc[mf][nf][1]);
            *(float2*)&po[(size_t)(r + 8) * E_DIM + c] =
                make_float2(acc[mf][nf][2], acc[mf][nf][3]);
        }
    }
}

// ---------------- reduce: out = sum of KSPLIT partials ----------------
__global__ void k_reduce(float* __restrict__ out, int n4) {
    int i = blockIdx.x * 256 + threadIdx.x;
    if (i >= n4) return;
    float4 a = ((const float4*)g_part[0])[i];
    float4 b = ((const float4*)g_part[1])[i];
    float4 c = ((const float4*)g_part[2])[i];
    float4 d = ((const float4*)g_part[3])[i];
    float4 r;
    r.x = (a.x + b.x) + (c.x + d.x);
    r.y = (a.y + b.y) + (c.y + d.y);
    r.z = (a.z + b.z) + (c.z + d.z);
    r.w = (a.w + b.w) + (c.w + d.w);
    ((float4*)out)[i] = r;
}

// ---------------- launch ----------------
extern "C" void kernel_launch(void* const* d_in, const int* in_sizes, int n_in,
                              void* d_out, int out_size) {
    const float* x  = (const float*)d_in[0];
    const float* A  = (const float*)d_in[1];
    const float* Bv = (const float*)d_in[2];
    const float* C  = (const float*)d_in[3];
    const float* M  = (const float*)d_in[4];
    const float* Mp = (const float*)d_in[5];
    const float* Mm = (const float*)d_in[6];
    float* out = (float*)d_out;

    static bool attr_set = false;
    if (!attr_set) {
        cudaFuncSetAttribute(k_gemm, cudaFuncAttributeMaxDynamicSharedMemorySize, SMEM_DYN);
        attr_set = true;
    }

    // k_gemm at launch #4 (the slot ncu captures).
    k_prep<<<128, 256>>>(C, Bv, M, Mp, Mm, 0);
    k_prep<<<128, 256>>>(C, Bv, M, Mp, Mm, 128);
    k_ckpt<<<512, 128>>>(x, A);

    dim3 grid(M_ROWS / 128, KSPLIT);
    k_gemm<<<grid, 512, SMEM_DYN>>>(x, A);

    int n4 = M_ROWS * E_DIM / 4;
    k_reduce<<<(n4 + 255) / 256, 256>>>(out, n4);
}

// round 11
// speedup vs baseline: 1.6839x; 1.0265x over previous
#include <cuda_runtime.h>
#include <cuda_fp16.h>
#include <cstdint>

// ---------------- problem dims ----------------
#define K_HALF 24
#define S_DIM  64
#define D_DIM  256
#define L_DIM  1024
#define B_SZ   4
#define KX     8
#define O_DIM  48                      // 2*K_HALF
#define K_G    16384                   // D_DIM * S_DIM  (k = d*64 + s)
#define K_TOT  18432                   // K_G + KX*D_DIM (k = 16384 + j*256 + d)
#define M_ROWS 4096                    // B_SZ * L_DIM
#define E_DIM  256
#define KSPLIT 4

// ---------------- scratch (device globals; no cudaMalloc allowed) ----------------
__device__ __half g_Pth[(size_t)E_DIM * K_TOT];                // 9.4 MB: [e][k] (B, K-major, fp16)
__device__ float  g_ck[(size_t)(M_ROWS / 32) * K_G];           //  8 MB: scan state entering each 32-row block
__device__ float  g_part[KSPLIT][(size_t)M_ROWS * E_DIM];      // 16 MB: split-K partials

// ---------------- helpers ----------------
__device__ __forceinline__ uint32_t smem_u32(const void* p) {
    uint32_t a;
    asm("{ .reg .u64 t; cvta.to.shared.u64 t, %1; cvt.u32.u64 %0, t; }" : "=r"(a) : "l"(p));
    return a;
}

__device__ __forceinline__ void cp_async16(uint32_t dst, const void* src) {
    asm volatile("cp.async.cg.shared.global [%0], [%1], 16;" :: "r"(dst), "l"(src));
}
__device__ __forceinline__ void cp_commit() {
    asm volatile("cp.async.commit_group;" ::: "memory");
}

// m16n8k16 fp16 mma, fp32 accumulate in place
__device__ __forceinline__ void mma16(float* d, const uint32_t* a, uint32_t b0, uint32_t b1) {
    asm volatile(
        "mma.sync.aligned.m16n8k16.row.col.f32.f16.f16.f32 "
        "{%0,%1,%2,%3},{%4,%5,%6,%7},{%8,%9},{%0,%1,%2,%3};"
        : "+f"(d[0]), "+f"(d[1]), "+f"(d[2]), "+f"(d[3])
        : "r"(a[0]), "r"(a[1]), "r"(a[2]), "r"(a[3]), "r"(b0), "r"(b1));
}

__device__ __forceinline__ void ldsm4(uint32_t* r, uint32_t addr) {
    asm volatile("ldmatrix.sync.aligned.m8n8.x4.shared.b16 {%0,%1,%2,%3}, [%4];"
        : "=r"(r[0]), "=r"(r[1]), "=r"(r[2]), "=r"(r[3]) : "r"(addr));
}

__device__ __forceinline__ void sts16(uint32_t addr, __half v) {
    unsigned short u = __half_as_ushort(v);
    asm volatile("st.shared.u16 [%0], %1;" :: "r"(addr), "h"(u));
}

// ---------------- kernel: precompute Pt[e][k] (fp16), half-d per call ----------
__global__ void k_prep(const float* __restrict__ C, const float* __restrict__ Bv,
                       const float* __restrict__ M, const float* __restrict__ Mp,
                       const float* __restrict__ Mm, int d0) {
    __shared__ float Wsh[O_DIM * E_DIM];   // 48 KB
    int d   = blockIdx.x + d0;
    int tid = threadIdx.x;
    int s   = tid & 63;
    int eg  = tid >> 6;

    for (int i = tid; i < O_DIM * E_DIM; i += 256) {
        int o = i >> 8, e = i & 255;
        Wsh[i] = (o < K_HALF) ? Mp[((size_t)o * D_DIM + d) * D_DIM + e]
                              : Mm[((size_t)(o - K_HALF) * D_DIM + d) * D_DIM + e];
    }
    __syncthreads();

    float cs[O_DIM];
#pragma unroll
    for (int o = 0; o < O_DIM; o++) cs[o] = C[s * O_DIM + o];
    float bv = Bv[s];

    for (int e = eg * 64; e < eg * 64 + 64; e++) {
        float acc = 0.0f;
#pragma unroll
        for (int o = 0; o < O_DIM; o++)
            acc = fmaf(cs[o], Wsh[o * E_DIM + e], acc);
        g_Pth[(size_t)e * K_TOT + d * S_DIM + s] = __float2half_rn(bv * acc);
    }

    if (s < KX) {
        int j = s;
        float mj[O_DIM];
#pragma unroll
        for (int o = 0; o < O_DIM; o++) mj[o] = M[o * KX + j];   // M is (48, 8, 1)
        for (int e = eg * 64; e < eg * 64 + 64; e++) {
            float acc = 0.0f;
#pragma unroll
            for (int o = 0; o < O_DIM; o++)
                acc = fmaf(mj[o], Wsh[o * E_DIM + e], acc);
            g_Pth[(size_t)e * K_TOT + K_G + j * D_DIM + d] = __float2half_rn(acc);
        }
    }
}

// ---------------- kernel: scan checkpoints every 32 rows (fp32) ----------------
__global__ void k_ckpt(const float* __restrict__ x, const float* __restrict__ A) {
    int s    = threadIdx.x & 63;
    int half = threadIdx.x >> 6;
    int bd   = blockIdx.x * 2 + half;   // 0..1023
    int b    = bd >> 8;
    int d    = bd & 255;

    float a = A[s];
    float h = 0.0f;
    const float* xp = x + (size_t)b * L_DIM * D_DIM + d;
    float* cp = g_ck + (size_t)(b * (L_DIM / 32)) * K_G + d * S_DIM + s;

#pragma unroll 1
    for (int lb = 0; lb < L_DIM / 32; lb++) {
        cp[(size_t)lb * K_G] = h;       // state entering row lb*32
#pragma unroll
        for (int i = 0; i < 32; i++)
            h = fmaf(h, a, xp[(size_t)(lb * 32 + i) * D_DIM]);
    }
}

// ---------------- fused fp16 GEMM  part[ki][m][e] = sum_k A[m][k]*Pt[e][k] -----
// CTA 128(M) x 256(N), 512 threads (16 warps 2x8, warp 64x32). KT=128 fp16 cols
// = 256B smem rows (two 128B swizzle atoms). 36 stages per chunk => half the
// barrier count of round 10. Producer: 32-row scan chains from g_ck.
#define KT    128
#define KCH   (K_TOT / KSPLIT)          // 4608
#define NSTG  (KCH / KT)                // 36
#define A_STG 32768                     // 128 rows * 256B
#define B_STG 65536                     // 256 rows * 256B
#define SMEM_DYN (2 * A_STG + 2 * B_STG)  // 196608

__global__ void __launch_bounds__(512, 1)
k_gemm(const float* __restrict__ x, const float* __restrict__ A) {
    extern __shared__ char smem[];
    uint32_t sb  = smem_u32(smem);
    uint32_t sbB = sb + 2 * A_STG;

    int tid  = threadIdx.x;
    int lane = tid & 31;
    int wid  = tid >> 5;                 // 0..15
    int wm   = wid >> 3;                 // 0..1
    int wn   = wid & 7;                  // 0..7
    int mi   = blockIdx.x;               // 0..31
    int ki   = blockIdx.y;               // 0..3
    int m0   = mi * 128;
    int k0   = ki * KCH;

    // producer coords: pc = column in 128-col stage, plb = 32-row block (0..3)
    int pc    = tid & 127;
    int plb   = tid >> 7;
    int phalf = pc >> 6;                 // which 128B atom in the row
    float a_reg = A[pc & 63];
    size_t ckrow = (size_t)(mi * 4 + plb) * K_G;
    uint32_t cchk  = (pc & 63) >> 3;
    uint32_t cbyte = (pc & 7) * 2;

    auto load_ck = [&](int st) -> float {
        int k = k0 + st * KT;
        if (st < NSTG && k < K_G)
            return g_ck[ckrow + (size_t)((k >> 6) + phalf) * S_DIM + (pc & 63)];
        return 0.0f;
    };

    // produce A stage st (128 rows x 128 fp16 cols) into buffer p
    auto produce = [&](int st, int p, float ck) {
        int k = k0 + st * KT;
        uint32_t abase = sb + p * A_STG + phalf * 128;
        if (k < K_G) {
            int d = (k >> 6) + phalf;
            float h = ck;
            const float* xp = x + (size_t)(m0 + plb * 32) * D_DIM + d;
#pragma unroll
            for (int i = 0; i < 32; i++) {
                h = fmaf(h, a_reg, xp[(size_t)i * D_DIM]);
                int r = plb * 32 + i;
                sts16(abase + r * 256 + ((cchk ^ (r & 7)) << 4) + cbyte,
                      __float2half_rn(h));
            }
        } else {
            int off = k - K_G;
            int j   = off >> 8;
            int dd  = (off & 255) + pc;
            const float* xp = x + (size_t)(m0 + plb * 32 - j) * D_DIM + dd;
            uint32_t cchk2  = (pc & 63) >> 3;   // note: col layout uses pc&63 within half
#pragma unroll
            for (int i = 0; i < 32; i++) {
                int gl = (m0 + plb * 32 + i) & (L_DIM - 1);
                float v = (gl >= j) ? xp[(size_t)i * D_DIM] : 0.0f;
                int r = plb * 32 + i;
                sts16(abase + r * 256 + ((cchk2 ^ (r & 7)) << 4) + cbyte,
                      __float2half_rn(v));
            }
        }
    };

    // cp.async B stage st (256 e-rows x 128 fp16) into buffer p
    auto cpB = [&](int st, int p) {
        uint32_t base = sbB + p * B_STG;
        int kf = k0 + st * KT;
#pragma unroll
        for (int q = 0; q < 8; q++) {
            int id = tid + q * 512;                 // 0..4095 16B chunks
            int r  = id >> 4;                       // e row (0..255)
            int ch = id & 15;                       // 16 chunks per 256B row
            int h2 = ch >> 3;
            int c7 = ch & 7;
            cp_async16(base + r * 256 + h2 * 128 + ((c7 ^ (r & 7)) << 4),
                       g_Pth + (size_t)r * K_TOT + kf + ch * 8);
        }
    };

    float acc[4][4][4];
#pragma unroll
    for (int i = 0; i < 4; i++)
#pragma unroll
        for (int j = 0; j < 4; j++)
#pragma unroll
            for (int c = 0; c < 4; c++) acc[i][j][c] = 0.0f;

    // ldmatrix per-lane address components (validated rounds 2-10):
    int sw   = lane & 7;
    int aRow = (lane & 7) + (((lane >> 3) & 1) << 3);
    int aCb  = lane >> 4;
    int bRow = (lane & 7) + ((lane >> 4) << 3);
    int bCb  = (lane >> 3) & 1;

    int lr = lane >> 2;
    int lc = lane & 3;

    // prologue
    produce(0, 0, load_ck(0));
    float ck_next = load_ck(1);
    cpB(0, 0); cp_commit();

    for (int ks = 0; ks < NSTG; ks++) {
        asm volatile("cp.async.wait_group 0;" ::: "memory");   // B(ks) complete
        __syncthreads();                                       // A(ks) visible; bufs free
        if (ks + 1 < NSTG) { cpB(ks + 1, (ks + 1) & 1); cp_commit(); }

        uint32_t aT = sb  + (ks & 1) * A_STG;
        uint32_t bT = sbB + (ks & 1) * B_STG;
        uint32_t aLane = aT + (wm * 64 + aRow) * 256;
        uint32_t bLane = bT + (wn * 32 + bRow) * 256;

        // ---- mma k-steps 0..3 (k cols 0..63, atom half 0) ----
#pragma unroll
        for (int kk = 0; kk < 4; kk++) {
            uint32_t bF[8];
#pragma unroll
            for (int nfp = 0; nfp < 2; nfp++)
                ldsm4(&bF[nfp * 4],
                      bLane + nfp * 16 * 256 + (((2 * kk + bCb) ^ sw) << 4));
            uint32_t aF[16];
#pragma unroll
            for (int mf = 0; mf < 4; mf++)
                ldsm4(&aF[mf * 4],
                      aLane + mf * 16 * 256 + (((2 * kk + aCb) ^ sw) << 4));
#pragma unroll
            for (int mf = 0; mf < 4; mf++)
#pragma unroll
                for (int nf = 0; nf < 4; nf++)
                    mma16(acc[mf][nf], &aF[mf * 4],
                          bF[(nf >> 1) * 4 + (nf & 1) * 2],
                          bF[(nf >> 1) * 4 + (nf & 1) * 2 + 1]);
        }

        // ---- producer for stage ks+1 (overlapped with mma) ----
        if (ks + 1 < NSTG) produce(ks + 1, (ks + 1) & 1, ck_next);
        ck_next = load_ck(ks + 2);

        // ---- mma k-steps 4..7 (k cols 64..127, atom half 1) ----
#pragma unroll
        for (int kk = 0; kk < 4; kk++) {
            uint32_t bF[8];
#pragma unroll
            for (int nfp = 0; nfp < 2; nfp++)
                ldsm4(&bF[nfp * 4],
                      bLane + 128 + nfp * 16 * 256 + (((2 * kk + bCb) ^ sw) << 4));
            uint32_t aF[16];
#pragma unroll
            for (int mf = 0; mf < 4; mf++)
                ldsm4(&aF[mf * 4],
                      aLane + 128 + mf * 16 * 256 + (((2 * kk + aCb) ^ sw) << 4));
#pragma unroll
            for (int mf = 0; mf < 4; mf++)
#pragma unroll
                for (int nf = 0; nf < 4; nf++)
                    mma16(acc[mf][nf], &aF[mf * 4],
                          bF[(nf >> 1) * 4 + (nf & 1) * 2],
                          bF[(nf >> 1) * 4 + (nf & 1) * 2 + 1]);
        }
    }

    // epilogue: plain stores to this split's partial buffer
    float* po = g_part[ki];
#pragma unroll
    for (int mf = 0; mf < 4; mf++) {
#pragma unroll
        for (int nf = 0; nf < 4; nf++) {
            int r = m0 + wm * 64 + mf * 16 + lr;
            int c = wn * 32 + nf * 8 + (lc << 1);
            *(float2*)&po[(size_t)r * E_DIM + c] =
                make_float2(acc[mf][nf][0], acc[mf][nf][1]);
            *(float2*)&po[(size_t)(r + 8) * E_DIM + c] =
                make_float2(acc[mf][nf][2], acc[mf][nf][3]);
        }
    }
}

// ---------------- reduce: out = sum of KSPLIT partials ----------------
__global__ void k_reduce(float* __restrict__ out, int n4) {
    int i = blockIdx.x * 256 + threadIdx.x;
    if (i >= n4) return;
    float4 a = ((const float4*)g_part[0])[i];
    float4 b = ((const float4*)g_part[1])[i];
    float4 c = ((const float4*)g_part[2])[i];
    float4 d = ((const float4*)g_part[3])[i];
    float4 r;
    r.x = (a.x + b.x) + (c.x + d.x);
    r.y = (a.y + b.y) + (c.y + d.y);
    r.z = (a.z + b.z) + (c.z + d.z);
    r.w = (a.w + b.w) + (c.w + d.w);
    ((float4*)out)[i] = r;
}

// ---------------- launch ----------------
extern "C" void kernel_launch(void* const* d_in, const int* in_sizes, int n_in,
                              void* d_out, int out_size) {
    const float* x  = (const float*)d_in[0];
    const float* A  = (const float*)d_in[1];
    const float* Bv = (const float*)d_in[2];
    const float* C  = (const float*)d_in[3];
    const float* M  = (const float*)d_in[4];
    const float* Mp = (const float*)d_in[5];
    const float* Mm = (const float*)d_in[6];
    float* out = (float*)d_out;

    static bool attr_set = false;
    if (!attr_set) {
        cudaFuncSetAttribute(k_gemm, cudaFuncAttributeMaxDynamicSharedMemorySize, SMEM_DYN);
        attr_set = true;
    }

    // k_gemm at launch #4 (the slot ncu captures).
    k_prep<<<128, 256>>>(C, Bv, M, Mp, Mm, 0);
    k_prep<<<128, 256>>>(C, Bv, M, Mp, Mm, 128);
    k_ckpt<<<512, 128>>>(x, A);

    dim3 grid(M_ROWS / 128, KSPLIT);
    k_gemm<<<grid, 512, SMEM_DYN>>>(x, A);

    int n4 = M_ROWS * E_DIM / 4;
    k_reduce<<<(n4 + 255) / 256, 256>>>(out, n4);
}